// round 2
// baseline (speedup 1.0000x reference)
#include <cuda_runtime.h>
#include <math.h>

// ---------------- problem dims ----------------
#define BB   4
#define N1_  9216
#define N2_  2304
#define N3_  576
#define D0_  128
#define D1_  256
#define D2_  512
#define DH_  2048

// ---------------- scratch pool (floats) ----------------
// zeroed region first (stats + S matrices, accumulated via atomics)
#define OFF_R1   0L               // 4*9216
#define OFF_C1   36864L           // 4*512
#define OFF_R2   38912L           // 4*2304
#define OFF_C2   48128L           // 4*512
#define OFF_R4   50176L           // 4*9216
#define OFF_C4   87040L           // 4*256
#define OFF_RA   88064L           // 4*2304
#define OFF_CA   97280L           // 4*512
#define OFF_ST1  99328L           // 4*512*512
#define OFF_ST2  1147904L         // 4*512*512
#define OFF_ST3  2196480L         // 4*256*256
#define OFF_ST4  2458624L         // 4*512*512
#define ZERO_CNT 3507200L
// non-zeroed scratch
#define OFF_E1   3507200L         // 4*9216*512
#define OFF_E2   22381568L        // 4*2304*512
#define OFF_E4   27100160L        // 4*9216*256
#define OFF_EA   36537344L        // 4*2304*512
#define OFF_T    41255936L        // 4*576*512
#define OFF_T3   42435584L        // 4*2304*256
#define OFF_A3   44794880L        // 4*2304*256
#define OFF_ATT  47154176L        // 4*576*512
#define OFF_AN   48333824L        // 4*576*512
#define OFF_H    49513472L        // 4*576*2048
#define OFF_AX   54232064L        // 4*576*2048
#define POOL_SZ  58950656L

__device__ float g_pool[POOL_SZ];

// ---------------- utility kernels ----------------
__global__ void zero_kernel(float* p, long n) {
    long i = (long)blockIdx.x * blockDim.x + threadIdx.x;
    long stride = (long)gridDim.x * blockDim.x;
    for (; i < n; i += stride) p[i] = 0.0f;
}

__global__ void recip_kernel(float* p, int n) {
    int i = blockIdx.x * blockDim.x + threadIdx.x;
    if (i < n) p[i] = 1.0f / p[i];
}

// ---------------- NT GEMM: C[b] = epilogue( A[b](MxK) @ B[b](NxK)^T ) ----------------
// 128x128 tile, 256 threads, 8x8 per thread, BK=16.
// EXP: write exp(acc), atomicAdd row/col sums of exp (softmax stats).
// else: v = alpha*(acc + bias); if ACCUM v += C; if ADDSRC v += addsrc; C = v.
// AMODE: 0 -> alpha=1 ; 1 -> alpha=sigmoid(*wscal) ; 2 -> alpha=(1-sigmoid)/2
template<bool EXP, bool BIAS, bool ACCUM, bool ADDSRC, int AMODE>
__global__ void __launch_bounds__(256) gemm_nt(
    const float* __restrict__ A, long aStr,
    const float* __restrict__ Bm, long bStr,
    float* __restrict__ C, long cStr,
    const float* __restrict__ bias,
    const float* __restrict__ addsrc, long sStr,
    const float* __restrict__ wscal,
    float* __restrict__ rowsum, float* __restrict__ colsum,
    int M, int N, int K)
{
    __shared__ float As[16][128];
    __shared__ float Bs[16][128];
    const int b  = blockIdx.z;
    const float* Ab = A  + (long)b * aStr;
    const float* Bb = Bm + (long)b * bStr;
    const int bm = blockIdx.y * 128;
    const int bn = blockIdx.x * 128;
    const int tid = threadIdx.x;
    const int tx = tid & 15, ty = tid >> 4;

    float acc[8][8];
#pragma unroll
    for (int i = 0; i < 8; i++)
#pragma unroll
        for (int j = 0; j < 8; j++) acc[i][j] = 0.0f;

    for (int k0 = 0; k0 < K; k0 += 16) {
#pragma unroll
        for (int l = 0; l < 2; l++) {
            int idx = tid + l * 256;          // 0..511
            int row = idx >> 2;
            int kq  = (idx & 3) << 2;
            float4 v = make_float4(0.f, 0.f, 0.f, 0.f);
            int gr = bm + row;
            if (gr < M) v = *(const float4*)(Ab + (long)gr * K + k0 + kq);
            As[kq + 0][row] = v.x; As[kq + 1][row] = v.y;
            As[kq + 2][row] = v.z; As[kq + 3][row] = v.w;
        }
#pragma unroll
        for (int l = 0; l < 2; l++) {
            int idx = tid + l * 256;
            int row = idx >> 2;
            int kq  = (idx & 3) << 2;
            float4 v = make_float4(0.f, 0.f, 0.f, 0.f);
            int gn = bn + row;
            if (gn < N) v = *(const float4*)(Bb + (long)gn * K + k0 + kq);
            Bs[kq + 0][row] = v.x; Bs[kq + 1][row] = v.y;
            Bs[kq + 2][row] = v.z; Bs[kq + 3][row] = v.w;
        }
        __syncthreads();
#pragma unroll
        for (int k = 0; k < 16; k++) {
            float a[8], bb[8];
#pragma unroll
            for (int i = 0; i < 8; i++) a[i]  = As[k][ty * 8 + i];
#pragma unroll
            for (int j = 0; j < 8; j++) bb[j] = Bs[k][tx * 8 + j];
#pragma unroll
            for (int i = 0; i < 8; i++)
#pragma unroll
                for (int j = 0; j < 8; j++) acc[i][j] += a[i] * bb[j];
        }
        __syncthreads();
    }

    if (EXP) {
        float rpart[8], cpart[8];
#pragma unroll
        for (int i = 0; i < 8; i++) { rpart[i] = 0.f; cpart[i] = 0.f; }
#pragma unroll
        for (int i = 0; i < 8; i++) {
            int row = bm + ty * 8 + i;
            if (row >= M) continue;
            float* Crow = C + (long)b * cStr + (long)row * N + bn + tx * 8;
#pragma unroll
            for (int j = 0; j < 8; j++) {
                float e = expf(acc[i][j]);
                Crow[j] = e;
                rpart[i] += e;
                cpart[j] += e;
            }
        }
#pragma unroll
        for (int i = 0; i < 8; i++) {
            int row = bm + ty * 8 + i;
            if (row < M) atomicAdd(rowsum + (long)b * M + row, rpart[i]);
        }
#pragma unroll
        for (int j = 0; j < 8; j++) {
            int col = bn + tx * 8 + j;
            if (col < N) atomicAdd(colsum + (long)b * N + col, cpart[j]);
        }
    } else {
        float alpha = 1.0f;
        if (AMODE != 0) {
            float f = 1.0f / (1.0f + expf(-wscal[0]));
            alpha = (AMODE == 1) ? f : (1.0f - f) * 0.5f;
        }
#pragma unroll
        for (int i = 0; i < 8; i++) {
            int row = bm + ty * 8 + i;
            if (row >= M) continue;
            float* Crow = C + (long)b * cStr + (long)row * N + bn + tx * 8;
            const float* Srow = ADDSRC ? (addsrc + (long)b * sStr + (long)row * N + bn + tx * 8) : nullptr;
#pragma unroll
            for (int j = 0; j < 8; j++) {
                float v = acc[i][j];
                if (BIAS) v += bias[bn + tx * 8 + j];
                v *= alpha;
                if (ACCUM)  v += Crow[j];
                if (ADDSRC) v += Srow[j];
                Crow[j] = v;
            }
        }
    }
}

// ---------------- TN GEMM for S = k^T q (transposed output, split-K) ----------------
// St[b][c'][c] += colinv[c'] * sum_k E[k][c] * (E[k][c'] * rowinv[k])
__global__ void __launch_bounds__(256) gemm_tn_s(
    const float* __restrict__ E, long eStr,
    const float* __restrict__ rinv,   // per batch, length K
    const float* __restrict__ cinv,   // per batch, length C
    float* __restrict__ St, long stStr,
    int C, int K, int splits)
{
    __shared__ float As[16][128];
    __shared__ float Bs[16][128];
    const int z = blockIdx.z;
    const int b = z / splits, s = z % splits;
    const int chunk = K / splits;
    const int kbase = s * chunk;
    const float* Eb = E + (long)b * eStr;
    const float* rb = rinv + (long)b * K;
    const int cm = blockIdx.y * 128;   // output rows: c  (A side)
    const int cn = blockIdx.x * 128;   // output cols: c' (B side, gets rowinv)
    const int tid = threadIdx.x;
    const int tx = tid & 15, ty = tid >> 4;

    float acc[8][8];
#pragma unroll
    for (int i = 0; i < 8; i++)
#pragma unroll
        for (int j = 0; j < 8; j++) acc[i][j] = 0.0f;

    for (int kk = 0; kk < chunk; kk += 16) {
        int k0 = kbase + kk;
#pragma unroll
        for (int l = 0; l < 2; l++) {
            int idx = tid + l * 256;
            int kr = idx >> 5;
            int cq = (idx & 31) << 2;
            float4 v = *(const float4*)(Eb + (long)(k0 + kr) * C + cm + cq);
            *(float4*)(&As[kr][cq]) = v;
        }
#pragma unroll
        for (int l = 0; l < 2; l++) {
            int idx = tid + l * 256;
            int kr = idx >> 5;
            int cq = (idx & 31) << 2;
            float rs = rb[k0 + kr];
            float4 v = *(const float4*)(Eb + (long)(k0 + kr) * C + cn + cq);
            v.x *= rs; v.y *= rs; v.z *= rs; v.w *= rs;
            *(float4*)(&Bs[kr][cq]) = v;
        }
        __syncthreads();
#pragma unroll
        for (int k = 0; k < 16; k++) {
            float a[8], bb[8];
#pragma unroll
            for (int i = 0; i < 8; i++) a[i]  = As[k][ty * 8 + i];
#pragma unroll
            for (int j = 0; j < 8; j++) bb[j] = Bs[k][tx * 8 + j];
#pragma unroll
            for (int i = 0; i < 8; i++)
#pragma unroll
                for (int j = 0; j < 8; j++) acc[i][j] += a[i] * bb[j];
        }
        __syncthreads();
    }

    const float* cb = cinv + (long)b * C;
    float* Sb = St + (long)b * stStr;
#pragma unroll
    for (int j = 0; j < 8; j++) {
        int col = cn + tx * 8 + j;
        float ci = cb[col];
#pragma unroll
        for (int i = 0; i < 8; i++) {
            int row = cm + ty * 8 + i;
            atomicAdd(Sb + (long)col * C + row, acc[i][j] * ci);
        }
    }
}

// ---------------- LayerNorm over last dim ----------------
__global__ void ln_rows(const float* __restrict__ X, const float* __restrict__ g,
                        const float* __restrict__ bb, float* __restrict__ Y, int C)
{
    long row = blockIdx.x;
    const float* x = X + row * C;
    float s = 0.f, s2 = 0.f;
    for (int c = threadIdx.x; c < C; c += blockDim.x) { float v = x[c]; s += v; s2 += v * v; }
    __shared__ float sh1[32], sh2[32];
    int lane = threadIdx.x & 31, wid = threadIdx.x >> 5;
#pragma unroll
    for (int o = 16; o; o >>= 1) {
        s  += __shfl_down_sync(0xffffffff, s,  o);
        s2 += __shfl_down_sync(0xffffffff, s2, o);
    }
    if (!lane) { sh1[wid] = s; sh2[wid] = s2; }
    __syncthreads();
    if (threadIdx.x == 0) {
        float a = 0.f, c2 = 0.f;
        int nw = blockDim.x >> 5;
        for (int i = 0; i < nw; i++) { a += sh1[i]; c2 += sh2[i]; }
        float mean = a / C;
        float var  = c2 / C - mean * mean;
        sh1[0] = mean; sh2[0] = rsqrtf(var + 1e-5f);
    }
    __syncthreads();
    float mean = sh1[0], rstd = sh2[0];
    for (int c = threadIdx.x; c < C; c += blockDim.x) {
        float v = x[c];
        Y[row * C + c] = (v - mean) * rstd * g[c] + bb[c];
    }
}

// ---------------- fused depthwise-3x3 conv + skip + LN + GELU ----------------
// h: [B, 576, 2048] channel-last, spatial 24x24. out = gelu(LN(dw(h)+bdw+h))
__global__ void __launch_bounds__(256) dwconv_ln_gelu(
    const float* __restrict__ H, const float* __restrict__ Wdw,
    const float* __restrict__ bdw, const float* __restrict__ g,
    const float* __restrict__ bt, float* __restrict__ AX)
{
    const int n = blockIdx.x;           // 0..575
    const int b = blockIdx.y;
    const int y = n / 24, x = n % 24;
    const float* Hb = H + (long)b * 576 * 2048;
    const int tid = threadIdx.x;

    float v[8];
    float s = 0.f, s2 = 0.f;
#pragma unroll
    for (int it = 0; it < 8; it++) {
        int c = tid + it * 256;
        float a = Hb[(long)n * 2048 + c] + bdw[c];   // skip + bias
#pragma unroll
        for (int ky = 0; ky < 3; ky++) {
            int yy = y + ky - 1;
            if (yy < 0 || yy > 23) continue;
#pragma unroll
            for (int kx = 0; kx < 3; kx++) {
                int xx = x + kx - 1;
                if (xx < 0 || xx > 23) continue;
                a += Wdw[c * 9 + ky * 3 + kx] * Hb[(long)(yy * 24 + xx) * 2048 + c];
            }
        }
        v[it] = a; s += a; s2 += a * a;
    }
    __shared__ float sh1[32], sh2[32];
    int lane = tid & 31, wid = tid >> 5;
#pragma unroll
    for (int o = 16; o; o >>= 1) {
        s  += __shfl_down_sync(0xffffffff, s,  o);
        s2 += __shfl_down_sync(0xffffffff, s2, o);
    }
    if (!lane) { sh1[wid] = s; sh2[wid] = s2; }
    __syncthreads();
    if (tid == 0) {
        float a = 0.f, c2 = 0.f;
        for (int i = 0; i < 8; i++) { a += sh1[i]; c2 += sh2[i]; }
        float mean = a / 2048.0f;
        float var  = c2 / 2048.0f - mean * mean;
        sh1[0] = mean; sh2[0] = rsqrtf(var + 1e-5f);
    }
    __syncthreads();
    float mean = sh1[0], rstd = sh2[0];
    float* out = AX + ((long)b * 576 + n) * 2048;
#pragma unroll
    for (int it = 0; it < 8; it++) {
        int c = tid + it * 256;
        float t = (v[it] - mean) * rstd * g[c] + bt[c];
        out[c] = 0.5f * t * (1.0f + erff(t * 0.70710678118654752f));
    }
}

// ---------------- host orchestration ----------------
extern "C" void kernel_launch(void* const* d_in, const int* in_sizes, int n_in,
                              void* d_out, int out_size)
{
    const float* x      = (const float*)d_in[0];
    const float* x2     = (const float*)d_in[1];
    const float* x3     = (const float*)d_in[2];
    const float* W_lin  = (const float*)d_in[3];
    const float* W_lin2 = (const float*)d_in[4];
    const float* W_lin3 = (const float*)d_in[5];
    const float* W_lin4 = (const float*)d_in[6];
    const float* w      = (const float*)d_in[7];
    const float* Wp1 = (const float*)d_in[8];  const float* bp1 = (const float*)d_in[9];
    const float* Wp2 = (const float*)d_in[10]; const float* bp2 = (const float*)d_in[11];
    const float* Wp3 = (const float*)d_in[12]; const float* bp3 = (const float*)d_in[13];
    const float* Wp4 = (const float*)d_in[14]; const float* bp4 = (const float*)d_in[15];
    const float* g_norm = (const float*)d_in[16]; const float* b_norm = (const float*)d_in[17];
    const float* Wfc1 = (const float*)d_in[18];   const float* bfc1  = (const float*)d_in[19];
    const float* Wdw  = (const float*)d_in[20];   const float* bdw   = (const float*)d_in[21];
    const float* g_ln1 = (const float*)d_in[22];  const float* b_ln1 = (const float*)d_in[23];
    const float* Wfc2 = (const float*)d_in[24];   const float* bfc2  = (const float*)d_in[25];

    float* pool = nullptr;
    cudaGetSymbolAddress((void**)&pool, g_pool);

    dim3 thr(256);

    // 0) zero stats + S buffers (atomic accumulation targets)
    zero_kernel<<<1024, 256>>>(pool, ZERO_CNT);

    // 1) E1 = exp(x @ W_lin^T) + stats  [B,9216,512]
    gemm_nt<true,false,false,false,0><<<dim3(4,72,BB), thr>>>(
        x, (long)N1_*D0_, W_lin, 0L, pool+OFF_E1, (long)N1_*D2_,
        nullptr, nullptr, 0L, nullptr, pool+OFF_R1, pool+OFF_C1, N1_, D2_, D0_);

    // 2) E2 = exp(x2 @ W_lin2^T) + stats  [B,2304,512]
    gemm_nt<true,false,false,false,0><<<dim3(4,18,BB), thr>>>(
        x2, (long)N2_*D1_, W_lin2, 0L, pool+OFF_E2, (long)N2_*D2_,
        nullptr, nullptr, 0L, nullptr, pool+OFF_R2, pool+OFF_C2, N2_, D2_, D1_);

    // 3) E4 = exp(x @ W_lin3^T) + stats  [B,9216,256]
    gemm_nt<true,false,false,false,0><<<dim3(2,72,BB), thr>>>(
        x, (long)N1_*D0_, W_lin3, 0L, pool+OFF_E4, (long)N1_*D1_,
        nullptr, nullptr, 0L, nullptr, pool+OFF_R4, pool+OFF_C4, N1_, D1_, D0_);

    // 4) reciprocal of stats (r1,c1,r2,c2,r4,c4 contiguous)
    recip_kernel<<<(88064 + 255) / 256, 256>>>(pool, 88064);

    // 5) St1 (transposed S) from E1, K=9216, split 4
    gemm_tn_s<<<dim3(4,4,BB*4), thr>>>(pool+OFF_E1, (long)N1_*D2_, pool+OFF_R1, pool+OFF_C1,
                                       pool+OFF_ST1, (long)D2_*D2_, D2_, N1_, 4);
    // 6) St2 from E2, K=2304, split 4
    gemm_tn_s<<<dim3(4,4,BB*4), thr>>>(pool+OFF_E2, (long)N2_*D2_, pool+OFF_R2, pool+OFF_C2,
                                       pool+OFF_ST2, (long)D2_*D2_, D2_, N2_, 4);
    // 7) St3 from E4, C=256, K=9216, split 16
    gemm_tn_s<<<dim3(2,2,BB*16), thr>>>(pool+OFF_E4, (long)N1_*D1_, pool+OFF_R4, pool+OFF_C4,
                                        pool+OFF_ST3, (long)D1_*D1_, D1_, N1_, 16);

    // 8) T = x3 @ St1^T(=S1)  [B,576,512]
    gemm_nt<false,false,false,false,0><<<dim3(4,5,BB), thr>>>(
        x3, (long)N3_*D2_, pool+OFF_ST1, (long)D2_*D2_, pool+OFF_T, (long)N3_*D2_,
        nullptr, nullptr, 0L, nullptr, nullptr, nullptr, N3_, D2_, D2_);
    // 9) ATT = x3 + other*(T @ Wp1^T + bp1)
    gemm_nt<false,true,false,true,2><<<dim3(4,5,BB), thr>>>(
        pool+OFF_T, (long)N3_*D2_, Wp1, 0L, pool+OFF_ATT, (long)N3_*D2_,
        bp1, x3, (long)N3_*D2_, w, nullptr, nullptr, N3_, D2_, D2_);

    // 10) T = x3 @ St2 ; 11) ATT += other*(T @ Wp2^T + bp2)
    gemm_nt<false,false,false,false,0><<<dim3(4,5,BB), thr>>>(
        x3, (long)N3_*D2_, pool+OFF_ST2, (long)D2_*D2_, pool+OFF_T, (long)N3_*D2_,
        nullptr, nullptr, 0L, nullptr, nullptr, nullptr, N3_, D2_, D2_);
    gemm_nt<false,true,true,false,2><<<dim3(4,5,BB), thr>>>(
        pool+OFF_T, (long)N3_*D2_, Wp2, 0L, pool+OFF_ATT, (long)N3_*D2_,
        bp2, nullptr, 0L, w, nullptr, nullptr, N3_, D2_, D2_);

    // 12) T3 = x2 @ St3   [B,2304,256]
    gemm_nt<false,false,false,false,0><<<dim3(2,18,BB), thr>>>(
        x2, (long)N2_*D1_, pool+OFF_ST3, (long)D1_*D1_, pool+OFF_T3, (long)N2_*D1_,
        nullptr, nullptr, 0L, nullptr, nullptr, nullptr, N2_, D1_, D1_);
    // 13) A3 = T3 @ Wp3^T + bp3
    gemm_nt<false,true,false,false,0><<<dim3(2,18,BB), thr>>>(
        pool+OFF_T3, (long)N2_*D1_, Wp3, 0L, pool+OFF_A3, (long)N2_*D1_,
        bp3, nullptr, 0L, nullptr, nullptr, nullptr, N2_, D1_, D1_);
    // 14) Ea = exp(A3 @ W_lin4^T) + stats  [B,2304,512]
    gemm_nt<true,false,false,false,0><<<dim3(4,18,BB), thr>>>(
        pool+OFF_A3, (long)N2_*D1_, W_lin4, 0L, pool+OFF_EA, (long)N2_*D2_,
        nullptr, nullptr, 0L, nullptr, pool+OFF_RA, pool+OFF_CA, N2_, D2_, D1_);
    // 15) reciprocal of ra,ca
    recip_kernel<<<(11264 + 255) / 256, 256>>>(pool + OFF_RA, 11264);
    // 16) St4 from Ea, K=2304, split 4
    gemm_tn_s<<<dim3(4,4,BB*4), thr>>>(pool+OFF_EA, (long)N2_*D2_, pool+OFF_RA, pool+OFF_CA,
                                       pool+OFF_ST4, (long)D2_*D2_, D2_, N2_, 4);
    // 17) T = x3 @ St4 ; 18) ATT += f*(T @ Wp4^T + bp4)
    gemm_nt<false,false,false,false,0><<<dim3(4,5,BB), thr>>>(
        x3, (long)N3_*D2_, pool+OFF_ST4, (long)D2_*D2_, pool+OFF_T, (long)N3_*D2_,
        nullptr, nullptr, 0L, nullptr, nullptr, nullptr, N3_, D2_, D2_);
    gemm_nt<false,true,true,false,1><<<dim3(4,5,BB), thr>>>(
        pool+OFF_T, (long)N3_*D2_, Wp4, 0L, pool+OFF_ATT, (long)N3_*D2_,
        bp4, nullptr, 0L, w, nullptr, nullptr, N3_, D2_, D2_);

    // 19) AN = LN(ATT)
    ln_rows<<<BB * N3_, 256>>>(pool + OFF_ATT, g_norm, b_norm, pool + OFF_AN, D2_);

    // 20) H = AN @ Wfc1^T + bfc1   [B,576,2048]
    gemm_nt<false,true,false,false,0><<<dim3(16,5,BB), thr>>>(
        pool+OFF_AN, (long)N3_*D2_, Wfc1, 0L, pool+OFF_H, (long)N3_*DH_,
        bfc1, nullptr, 0L, nullptr, nullptr, nullptr, N3_, DH_, D2_);

    // 21) AX = gelu(LN(dwconv(H)+bdw+H))
    dwconv_ln_gelu<<<dim3(N3_, BB), 256>>>(pool + OFF_H, Wdw, bdw, g_ln1, b_ln1, pool + OFF_AX);

    // 22) out = ATT + AX @ Wfc2^T + bfc2
    gemm_nt<false,true,false,true,0><<<dim3(4,5,BB), thr>>>(
        pool+OFF_AX, (long)N3_*DH_, Wfc2, 0L, (float*)d_out, (long)N3_*D2_,
        bfc2, pool+OFF_ATT, (long)N3_*D2_, nullptr, nullptr, nullptr, N3_, D2_, DH_);
}

// round 4
// speedup vs baseline: 3.2582x; 3.2582x over previous
#include <cuda_runtime.h>
#include <math.h>
#include <stdint.h>

// ---------------- problem dims ----------------
#define BB   4
#define N1_  9216
#define N2_  2304
#define N3_  576
#define D0_  128
#define D1_  256
#define D2_  512
#define DH_  2048

// ---------------- scratch pool (floats) ----------------
#define OFF_R1   0L
#define OFF_C1   36864L
#define OFF_R2   38912L
#define OFF_C2   48128L
#define OFF_R4   50176L
#define OFF_C4   87040L
#define OFF_RA   88064L
#define OFF_CA   97280L
#define OFF_ST1  99328L
#define OFF_ST2  1147904L
#define OFF_ST3  2196480L
#define OFF_ST4  2458624L
#define ZERO_CNT 3507200L
#define OFF_ET1  3507200L
#define OFF_ET2  22381568L
#define OFF_ET4  27100160L
#define OFF_ETA  36537344L
#define OFF_T    41255936L
#define OFF_T3   42435584L
#define OFF_A3   44794880L
#define OFF_ATT  47154176L
#define OFF_AN   48333824L
#define OFF_H    49513472L
#define OFF_AX   54232064L
#define POOL_SZ  58950656L

__device__ float g_pool[POOL_SZ];

// ---------------- helpers ----------------
__device__ __forceinline__ float to_tf32(float x) {
    float y;
    asm("cvt.rna.tf32.f32 %0, %1;" : "=f"(y) : "f"(x));
    return y;
}
__device__ __forceinline__ float4 rnd4(float4 v) {
    v.x = to_tf32(v.x); v.y = to_tf32(v.y); v.z = to_tf32(v.z); v.w = to_tf32(v.w);
    return v;
}
__device__ __forceinline__ void mma_tf32(float* d, const uint32_t* a, const uint32_t* bf) {
    asm volatile(
        "mma.sync.aligned.m16n8k8.row.col.f32.tf32.tf32.f32 "
        "{%0,%1,%2,%3}, {%4,%5,%6,%7}, {%8,%9}, {%0,%1,%2,%3};"
        : "+f"(d[0]), "+f"(d[1]), "+f"(d[2]), "+f"(d[3])
        : "r"(a[0]), "r"(a[1]), "r"(a[2]), "r"(a[3]), "r"(bf[0]), "r"(bf[1]));
}

// ================= tf32 mma.sync NT GEMM =================
// D[m][n] = sum_k A[m][k] * B[n][k], 128x128 CTA tile, BK=16, 128 threads (4 warps, 64x64 each),
// double-buffered smem (stride-20 pad, conflict-free fragment loads).
// EPI 0: C[m][n] = acc
// EPI 1: e = exp(acc); Et[n][m] = e; atomic rowsum[m] += sum_n e; colsum[n] += sum_m e
// EPI 2: C[m][n] = alpha*(acc + bias[n]) + (addsrc ? addsrc[m][n] : 0)
// EPI 3: C[m][n] += alpha*(acc + bias[n])
// EPI 4: atomicAdd(C[m][n], acc * mscale[m])           (split-K S-gemm, coalesced)
// AMODE: 0 alpha=1 ; 1 alpha=sigmoid(*wscal) ; 2 alpha=(1-sigmoid)/2
// KSC: B *= kscale[k] at load ; MSC: use mscale in EPI4
template<int EPI, int AMODE, bool KSC, bool MSC>
__global__ void __launch_bounds__(128, 2) tgemm(
    const float* __restrict__ A, long aStr, int lda,
    const float* __restrict__ Bm, long bStr, int ldb,
    float* __restrict__ C, long cStr, int ldc,
    int mTot, int nTot, int kTot, int splits,
    const float* __restrict__ bias,
    const float* __restrict__ addsrc,
    const float* __restrict__ wscal,
    float* __restrict__ rowsum, float* __restrict__ colsum,
    const float* __restrict__ kscale, const float* __restrict__ mscale)
{
    __shared__ float As[2][128][20];
    __shared__ float Bs[2][128][20];

    const int z = blockIdx.z;
    const int b = z / splits, sp = z % splits;
    const int Kc = kTot / splits;
    const int kbase = sp * Kc;
    const int nt = Kc >> 4;

    const float* Ab = A + (long)b * aStr;
    const float* Bb = Bm + (long)b * bStr;
    const float* ksc_b = KSC ? (kscale + (long)b * kTot) : nullptr;

    const int bm = blockIdx.y * 128;
    const int bn = blockIdx.x * 128;
    const int tid = threadIdx.x;
    const int wid = tid >> 5, lane = tid & 31;
    const int wm = wid & 1, wn = wid >> 1;        // warp tile: rows wm*64, cols wn*64
    const int lr = lane >> 2, lc = lane & 3;

    float acc[4][8][4];
#pragma unroll
    for (int i = 0; i < 4; i++)
#pragma unroll
        for (int j = 0; j < 8; j++)
#pragma unroll
            for (int r = 0; r < 4; r++) acc[i][j][r] = 0.0f;

    // ---- initial tile -> buffer 0 ----
    {
        const int k0 = kbase;
#pragma unroll
        for (int l = 0; l < 4; l++) {
            int idx = tid + (l << 7);
            int row = idx >> 2, kq = (idx & 3) << 2;
            int gr = bm + row;
            float4 va = make_float4(0.f, 0.f, 0.f, 0.f);
            if (gr < mTot) va = *(const float4*)(Ab + (long)gr * lda + k0 + kq);
            float4 vb = *(const float4*)(Bb + (long)(bn + row) * ldb + k0 + kq);
            if (KSC) {
                float4 ks = *(const float4*)(ksc_b + k0 + kq);
                vb.x *= ks.x; vb.y *= ks.y; vb.z *= ks.z; vb.w *= ks.w;
            }
            *(float4*)(&As[0][row][kq]) = rnd4(va);
            *(float4*)(&Bs[0][row][kq]) = rnd4(vb);
        }
    }
    __syncthreads();

    for (int t = 0; t < nt; t++) {
        const int cur = t & 1;
        float4 ra[4], rb[4];
        if (t + 1 < nt) {
            const int k0 = kbase + ((t + 1) << 4);
#pragma unroll
            for (int l = 0; l < 4; l++) {
                int idx = tid + (l << 7);
                int row = idx >> 2, kq = (idx & 3) << 2;
                int gr = bm + row;
                float4 va = make_float4(0.f, 0.f, 0.f, 0.f);
                if (gr < mTot) va = *(const float4*)(Ab + (long)gr * lda + k0 + kq);
                ra[l] = va;
                float4 vb = *(const float4*)(Bb + (long)(bn + row) * ldb + k0 + kq);
                if (KSC) {
                    float4 ks = *(const float4*)(ksc_b + k0 + kq);
                    vb.x *= ks.x; vb.y *= ks.y; vb.z *= ks.z; vb.w *= ks.w;
                }
                rb[l] = vb;
            }
        }
        // ---- MMA on buffer cur ----
#pragma unroll
        for (int ks = 0; ks < 2; ks++) {
            const int kb = ks << 3;
            uint32_t af[4][4];
#pragma unroll
            for (int i = 0; i < 4; i++) {
                int r0 = wm * 64 + i * 16 + lr;
                af[i][0] = __float_as_uint(As[cur][r0][kb + lc]);
                af[i][1] = __float_as_uint(As[cur][r0 + 8][kb + lc]);
                af[i][2] = __float_as_uint(As[cur][r0][kb + lc + 4]);
                af[i][3] = __float_as_uint(As[cur][r0 + 8][kb + lc + 4]);
            }
            uint32_t bf[8][2];
#pragma unroll
            for (int j = 0; j < 8; j++) {
                int n0 = wn * 64 + j * 8 + lr;
                bf[j][0] = __float_as_uint(Bs[cur][n0][kb + lc]);
                bf[j][1] = __float_as_uint(Bs[cur][n0][kb + lc + 4]);
            }
#pragma unroll
            for (int i = 0; i < 4; i++)
#pragma unroll
                for (int j = 0; j < 8; j++)
                    mma_tf32(acc[i][j], af[i], bf[j]);
        }
        if (t + 1 < nt) {
            const int nxt = (t + 1) & 1;
#pragma unroll
            for (int l = 0; l < 4; l++) {
                int idx = tid + (l << 7);
                int row = idx >> 2, kq = (idx & 3) << 2;
                *(float4*)(&As[nxt][row][kq]) = rnd4(ra[l]);
                *(float4*)(&Bs[nxt][row][kq]) = rnd4(rb[l]);
            }
        }
        __syncthreads();
    }

    // ---- epilogue ----
    float alpha = 1.0f;
    if (AMODE == 1) alpha = 1.0f / (1.0f + expf(-wscal[0]));
    if (AMODE == 2) alpha = (1.0f - 1.0f / (1.0f + expf(-wscal[0]))) * 0.5f;

    float* Cb = C + (long)b * cStr;

    if (EPI == 1) {
        float rs[4][2];
#pragma unroll
        for (int i = 0; i < 4; i++) { rs[i][0] = 0.f; rs[i][1] = 0.f; }
#pragma unroll
        for (int j = 0; j < 8; j++) {
            int col0 = bn + wn * 64 + j * 8 + lc * 2;
            float cs0 = 0.f, cs1 = 0.f;
#pragma unroll
            for (int i = 0; i < 4; i++) {
                int r0 = bm + wm * 64 + i * 16 + lr;
                float e0 = expf(acc[i][j][0]);
                float e1 = expf(acc[i][j][1]);
                float e2 = expf(acc[i][j][2]);
                float e3 = expf(acc[i][j][3]);
                Cb[(long)col0 * ldc + r0]           = e0;
                Cb[(long)(col0 + 1) * ldc + r0]     = e1;
                Cb[(long)col0 * ldc + r0 + 8]       = e2;
                Cb[(long)(col0 + 1) * ldc + r0 + 8] = e3;
                cs0 += e0 + e2; cs1 += e1 + e3;
                rs[i][0] += e0 + e1; rs[i][1] += e2 + e3;
            }
#pragma unroll
            for (int o = 4; o <= 16; o <<= 1) {
                cs0 += __shfl_xor_sync(0xffffffff, cs0, o);
                cs1 += __shfl_xor_sync(0xffffffff, cs1, o);
            }
            if (lane < 4) {
                atomicAdd(colsum + (long)b * nTot + col0, cs0);
                atomicAdd(colsum + (long)b * nTot + col0 + 1, cs1);
            }
        }
#pragma unroll
        for (int i = 0; i < 4; i++)
#pragma unroll
            for (int h = 0; h < 2; h++) {
                float v = rs[i][h];
                v += __shfl_xor_sync(0xffffffff, v, 1);
                v += __shfl_xor_sync(0xffffffff, v, 2);
                if (lc == 0) {
                    int r = bm + wm * 64 + i * 16 + lr + h * 8;
                    atomicAdd(rowsum + (long)b * mTot + r, v);
                }
            }
    } else if (EPI == 4) {
        const float* msc = MSC ? (mscale + (long)b * mTot) : nullptr;
#pragma unroll
        for (int i = 0; i < 4; i++) {
            int r0 = bm + wm * 64 + i * 16 + lr;
            float s0 = MSC ? msc[r0] : 1.0f;
            float s1 = MSC ? msc[r0 + 8] : 1.0f;
#pragma unroll
            for (int j = 0; j < 8; j++) {
                int col0 = bn + wn * 64 + j * 8 + lc * 2;
                atomicAdd(Cb + (long)r0 * ldc + col0,           acc[i][j][0] * s0);
                atomicAdd(Cb + (long)r0 * ldc + col0 + 1,       acc[i][j][1] * s0);
                atomicAdd(Cb + (long)(r0 + 8) * ldc + col0,     acc[i][j][2] * s1);
                atomicAdd(Cb + (long)(r0 + 8) * ldc + col0 + 1, acc[i][j][3] * s1);
            }
        }
    } else {
#pragma unroll
        for (int i = 0; i < 4; i++) {
#pragma unroll
            for (int h = 0; h < 2; h++) {
                int r = bm + wm * 64 + i * 16 + lr + h * 8;
                if (r >= mTot) continue;
                float* Crow = Cb + (long)r * ldc;
                const float* Srow = (EPI == 2 && addsrc) ? (addsrc + (long)b * cStr + (long)r * ldc) : nullptr;
#pragma unroll
                for (int j = 0; j < 8; j++) {
                    int col0 = bn + wn * 64 + j * 8 + lc * 2;
                    float v0 = acc[i][j][h * 2 + 0];
                    float v1 = acc[i][j][h * 2 + 1];
                    if (EPI == 2) {
                        v0 = alpha * (v0 + bias[col0]);
                        v1 = alpha * (v1 + bias[col0 + 1]);
                        if (Srow) { v0 += Srow[col0]; v1 += Srow[col0 + 1]; }
                    }
                    if (EPI == 3) {
                        float2 old = *(const float2*)(Crow + col0);
                        v0 = old.x + alpha * (v0 + bias[col0]);
                        v1 = old.y + alpha * (v1 + bias[col0 + 1]);
                    }
                    float2 o; o.x = v0; o.y = v1;
                    *(float2*)(Crow + col0) = o;
                }
            }
        }
    }
}

// ---------------- utility kernels ----------------
__global__ void zero_kernel(float* p, long n) {
    long i = (long)blockIdx.x * blockDim.x + threadIdx.x;
    long stride = (long)gridDim.x * blockDim.x;
    for (; i < n; i += stride) p[i] = 0.0f;
}
__global__ void recip_kernel(float* p, int n) {
    int i = blockIdx.x * blockDim.x + threadIdx.x;
    if (i < n) p[i] = 1.0f / p[i];
}

__global__ void ln_rows(const float* __restrict__ X, const float* __restrict__ g,
                        const float* __restrict__ bb, float* __restrict__ Y, int C)
{
    long row = blockIdx.x;
    const float* x = X + row * C;
    float s = 0.f, s2 = 0.f;
    for (int c = threadIdx.x; c < C; c += blockDim.x) { float v = x[c]; s += v; s2 += v * v; }
    __shared__ float sh1[32], sh2[32];
    int lane = threadIdx.x & 31, wid = threadIdx.x >> 5;
#pragma unroll
    for (int o = 16; o; o >>= 1) {
        s  += __shfl_down_sync(0xffffffff, s,  o);
        s2 += __shfl_down_sync(0xffffffff, s2, o);
    }
    if (!lane) { sh1[wid] = s; sh2[wid] = s2; }
    __syncthreads();
    if (threadIdx.x == 0) {
        float a = 0.f, c2 = 0.f;
        int nw = blockDim.x >> 5;
        for (int i = 0; i < nw; i++) { a += sh1[i]; c2 += sh2[i]; }
        float mean = a / C;
        float var  = c2 / C - mean * mean;
        sh1[0] = mean; sh2[0] = rsqrtf(var + 1e-5f);
    }
    __syncthreads();
    float mean = sh1[0], rstd = sh2[0];
    for (int c = threadIdx.x; c < C; c += blockDim.x) {
        float v = x[c];
        Y[row * C + c] = (v - mean) * rstd * g[c] + bb[c];
    }
}

__global__ void __launch_bounds__(256) dwconv_ln_gelu(
    const float* __restrict__ H, const float* __restrict__ Wdw,
    const float* __restrict__ bdw, const float* __restrict__ g,
    const float* __restrict__ bt, float* __restrict__ AX)
{
    const int n = blockIdx.x;
    const int b = blockIdx.y;
    const int y = n / 24, x = n % 24;
    const float* Hb = H + (long)b * 576 * 2048;
    const int tid = threadIdx.x;

    float v[8];
    float s = 0.f, s2 = 0.f;
#pragma unroll
    for (int it = 0; it < 8; it++) {
        int c = tid + it * 256;
        float a = Hb[(long)n * 2048 + c] + bdw[c];
#pragma unroll
        for (int ky = 0; ky < 3; ky++) {
            int yy = y + ky - 1;
            if (yy < 0 || yy > 23) continue;
#pragma unroll
            for (int kx = 0; kx < 3; kx++) {
                int xx = x + kx - 1;
                if (xx < 0 || xx > 23) continue;
                a += Wdw[c * 9 + ky * 3 + kx] * Hb[(long)(yy * 24 + xx) * 2048 + c];
            }
        }
        v[it] = a; s += a; s2 += a * a;
    }
    __shared__ float sh1[32], sh2[32];
    int lane = tid & 31, wid = tid >> 5;
#pragma unroll
    for (int o = 16; o; o >>= 1) {
        s  += __shfl_down_sync(0xffffffff, s,  o);
        s2 += __shfl_down_sync(0xffffffff, s2, o);
    }
    if (!lane) { sh1[wid] = s; sh2[wid] = s2; }
    __syncthreads();
    if (tid == 0) {
        float a = 0.f, c2 = 0.f;
        for (int i = 0; i < 8; i++) { a += sh1[i]; c2 += sh2[i]; }
        float mean = a / 2048.0f;
        float var  = c2 / 2048.0f - mean * mean;
        sh1[0] = mean; sh2[0] = rsqrtf(var + 1e-5f);
    }
    __syncthreads();
    float mean = sh1[0], rstd = sh2[0];
    float* out = AX + ((long)b * 576 + n) * 2048;
#pragma unroll
    for (int it = 0; it < 8; it++) {
        int c = tid + it * 256;
        float t = (v[it] - mean) * rstd * g[c] + bt[c];
        out[c] = 0.5f * t * (1.0f + erff(t * 0.70710678118654752f));
    }
}

// ---------------- host orchestration ----------------
extern "C" void kernel_launch(void* const* d_in, const int* in_sizes, int n_in,
                              void* d_out, int out_size)
{
    const float* x      = (const float*)d_in[0];
    const float* x2     = (const float*)d_in[1];
    const float* x3     = (const float*)d_in[2];
    const float* W_lin  = (const float*)d_in[3];
    const float* W_lin2 = (const float*)d_in[4];
    const float* W_lin3 = (const float*)d_in[5];
    const float* W_lin4 = (const float*)d_in[6];
    const float* w      = (const float*)d_in[7];
    const float* Wp1 = (const float*)d_in[8];  const float* bp1 = (const float*)d_in[9];
    const float* Wp2 = (const float*)d_in[10]; const float* bp2 = (const float*)d_in[11];
    const float* Wp3 = (const float*)d_in[12]; const float* bp3 = (const float*)d_in[13];
    const float* Wp4 = (const float*)d_in[14]; const float* bp4 = (const float*)d_in[15];
    const float* g_norm = (const float*)d_in[16]; const float* b_norm = (const float*)d_in[17];
    const float* Wfc1 = (const float*)d_in[18];   const float* bfc1  = (const float*)d_in[19];
    const float* Wdw  = (const float*)d_in[20];   const float* bdw   = (const float*)d_in[21];
    const float* g_ln1 = (const float*)d_in[22];  const float* b_ln1 = (const float*)d_in[23];
    const float* Wfc2 = (const float*)d_in[24];   const float* bfc2  = (const float*)d_in[25];

    float* pool = nullptr;
    cudaGetSymbolAddress((void**)&pool, g_pool);

    // 0) zero stats + S accumulators
    zero_kernel<<<1024, 256>>>(pool, ZERO_CNT);

    // 1) Et1 = exp(x @ W_lin^T)^T + softmax stats     [B,512,9216]
    tgemm<1,0,false,false><<<dim3(4,72,BB), 128>>>(
        x, (long)N1_*D0_, D0_, W_lin, 0L, D0_,
        pool+OFF_ET1, (long)D2_*N1_, N1_,
        N1_, D2_, D0_, 1,
        nullptr, nullptr, nullptr, pool+OFF_R1, pool+OFF_C1, nullptr, nullptr);

    // 2) Et2 = exp(x2 @ W_lin2^T)^T + stats           [B,512,2304]
    tgemm<1,0,false,false><<<dim3(4,18,BB), 128>>>(
        x2, (long)N2_*D1_, D1_, W_lin2, 0L, D1_,
        pool+OFF_ET2, (long)D2_*N2_, N2_,
        N2_, D2_, D1_, 1,
        nullptr, nullptr, nullptr, pool+OFF_R2, pool+OFF_C2, nullptr, nullptr);

    // 3) Et4 = exp(x @ W_lin3^T)^T + stats            [B,256,9216]
    tgemm<1,0,false,false><<<dim3(2,72,BB), 128>>>(
        x, (long)N1_*D0_, D0_, W_lin3, 0L, D0_,
        pool+OFF_ET4, (long)D1_*N1_, N1_,
        N1_, D1_, D0_, 1,
        nullptr, nullptr, nullptr, pool+OFF_R4, pool+OFF_C4, nullptr, nullptr);

    // 4) reciprocal of stats (R1,C1,R2,C2,R4,C4)
    recip_kernel<<<(88064 + 255) / 256, 256>>>(pool, 88064);

    // 5) St1[c][c3] = cinv[c] * sum_tok Et1[c][tok]*rinv[tok]*Et1[c3][tok]   split-K 8
    tgemm<4,0,true,true><<<dim3(4,4,BB*8), 128>>>(
        pool+OFF_ET1, (long)D2_*N1_, N1_, pool+OFF_ET1, (long)D2_*N1_, N1_,
        pool+OFF_ST1, (long)D2_*D2_, D2_,
        D2_, D2_, N1_, 8,
        nullptr, nullptr, nullptr, nullptr, nullptr, pool+OFF_R1, pool+OFF_C1);

    // 6) St2 (K=2304, split 4)
    tgemm<4,0,true,true><<<dim3(4,4,BB*4), 128>>>(
        pool+OFF_ET2, (long)D2_*N2_, N2_, pool+OFF_ET2, (long)D2_*N2_, N2_,
        pool+OFF_ST2, (long)D2_*D2_, D2_,
        D2_, D2_, N2_, 4,
        nullptr, nullptr, nullptr, nullptr, nullptr, pool+OFF_R2, pool+OFF_C2);

    // 7) St3 (C=256, K=9216, split 8)
    tgemm<4,0,true,true><<<dim3(2,2,BB*8), 128>>>(
        pool+OFF_ET4, (long)D1_*N1_, N1_, pool+OFF_ET4, (long)D1_*N1_, N1_,
        pool+OFF_ST3, (long)D1_*D1_, D1_,
        D1_, D1_, N1_, 8,
        nullptr, nullptr, nullptr, nullptr, nullptr, pool+OFF_R4, pool+OFF_C4);

    // 8) T = x3 @ S1   (B operand = St1 row-major)
    tgemm<0,0,false,false><<<dim3(4,5,BB), 128>>>(
        x3, (long)N3_*D2_, D2_, pool+OFF_ST1, (long)D2_*D2_, D2_,
        pool+OFF_T, (long)N3_*D2_, D2_,
        N3_, D2_, D2_, 1,
        nullptr, nullptr, nullptr, nullptr, nullptr, nullptr, nullptr);
    // 9) ATT = x3 + other*(T @ Wp1^T + bp1)
    tgemm<2,2,false,false><<<dim3(4,5,BB), 128>>>(
        pool+OFF_T, (long)N3_*D2_, D2_, Wp1, 0L, D2_,
        pool+OFF_ATT, (long)N3_*D2_, D2_,
        N3_, D2_, D2_, 1,
        bp1, x3, w, nullptr, nullptr, nullptr, nullptr);

    // 10) T = x3 @ S2 ; ATT += other*(T @ Wp2^T + bp2)
    tgemm<0,0,false,false><<<dim3(4,5,BB), 128>>>(
        x3, (long)N3_*D2_, D2_, pool+OFF_ST2, (long)D2_*D2_, D2_,
        pool+OFF_T, (long)N3_*D2_, D2_,
        N3_, D2_, D2_, 1,
        nullptr, nullptr, nullptr, nullptr, nullptr, nullptr, nullptr);
    tgemm<3,2,false,false><<<dim3(4,5,BB), 128>>>(
        pool+OFF_T, (long)N3_*D2_, D2_, Wp2, 0L, D2_,
        pool+OFF_ATT, (long)N3_*D2_, D2_,
        N3_, D2_, D2_, 1,
        bp2, nullptr, w, nullptr, nullptr, nullptr, nullptr);

    // 12) T3 = x2 @ S3   [B,2304,256]
    tgemm<0,0,false,false><<<dim3(2,18,BB), 128>>>(
        x2, (long)N2_*D1_, D1_, pool+OFF_ST3, (long)D1_*D1_, D1_,
        pool+OFF_T3, (long)N2_*D1_, D1_,
        N2_, D1_, D1_, 1,
        nullptr, nullptr, nullptr, nullptr, nullptr, nullptr, nullptr);
    // 13) A3 = T3 @ Wp3^T + bp3
    tgemm<2,0,false,false><<<dim3(2,18,BB), 128>>>(
        pool+OFF_T3, (long)N2_*D1_, D1_, Wp3, 0L, D1_,
        pool+OFF_A3, (long)N2_*D1_, D1_,
        N2_, D1_, D1_, 1,
        bp3, nullptr, nullptr, nullptr, nullptr, nullptr, nullptr);
    // 14) EtA = exp(A3 @ W_lin4^T)^T + stats   [B,512,2304]
    tgemm<1,0,false,false><<<dim3(4,18,BB), 128>>>(
        pool+OFF_A3, (long)N2_*D1_, D1_, W_lin4, 0L, D1_,
        pool+OFF_ETA, (long)D2_*N2_, N2_,
        N2_, D2_, D1_, 1,
        nullptr, nullptr, nullptr, pool+OFF_RA, pool+OFF_CA, nullptr, nullptr);
    // 15) reciprocal of RA,CA
    recip_kernel<<<(11264 + 255) / 256, 256>>>(pool + OFF_RA, 11264);
    // 16) St4 (K=2304, split 4)
    tgemm<4,0,true,true><<<dim3(4,4,BB*4), 128>>>(
        pool+OFF_ETA, (long)D2_*N2_, N2_, pool+OFF_ETA, (long)D2_*N2_, N2_,
        pool+OFF_ST4, (long)D2_*D2_, D2_,
        D2_, D2_, N2_, 4,
        nullptr, nullptr, nullptr, nullptr, nullptr, pool+OFF_RA, pool+OFF_CA);
    // 17) T = x3 @ S4 ; ATT += f*(T @ Wp4^T + bp4)
    tgemm<0,0,false,false><<<dim3(4,5,BB), 128>>>(
        x3, (long)N3_*D2_, D2_, pool+OFF_ST4, (long)D2_*D2_, D2_,
        pool+OFF_T, (long)N3_*D2_, D2_,
        N3_, D2_, D2_, 1,
        nullptr, nullptr, nullptr, nullptr, nullptr, nullptr, nullptr);
    tgemm<3,1,false,false><<<dim3(4,5,BB), 128>>>(
        pool+OFF_T, (long)N3_*D2_, D2_, Wp4, 0L, D2_,
        pool+OFF_ATT, (long)N3_*D2_, D2_,
        N3_, D2_, D2_, 1,
        bp4, nullptr, w, nullptr, nullptr, nullptr, nullptr);

    // 19) AN = LN(ATT)
    ln_rows<<<BB * N3_, 256>>>(pool + OFF_ATT, g_norm, b_norm, pool + OFF_AN, D2_);

    // 20) H = AN @ Wfc1^T + bfc1   [B,576,2048]
    tgemm<2,0,false,false><<<dim3(16,5,BB), 128>>>(
        pool+OFF_AN, (long)N3_*D2_, D2_, Wfc1, 0L, D2_,
        pool+OFF_H, (long)N3_*DH_, DH_,
        N3_, DH_, D2_, 1,
        bfc1, nullptr, nullptr, nullptr, nullptr, nullptr, nullptr);

    // 21) AX = gelu(LN(dwconv(H)+bdw+H))
    dwconv_ln_gelu<<<dim3(N3_, BB), 256>>>(pool + OFF_H, Wdw, bdw, g_ln1, b_ln1, pool + OFF_AX);

    // 22) out = ATT + AX @ Wfc2^T + bfc2
    tgemm<2,0,false,false><<<dim3(4,5,BB), 128>>>(
        pool+OFF_AX, (long)N3_*DH_, DH_, Wfc2, 0L, DH_,
        (float*)d_out, (long)N3_*D2_, D2_,
        N3_, D2_, DH_, 1,
        bfc2, pool+OFF_ATT, nullptr, nullptr, nullptr, nullptr, nullptr);
}